// round 3
// baseline (speedup 1.0000x reference)
#include <cuda_runtime.h>
#include <cstddef>

// pred_raw[b, 4h+i, 4w+j] = y[b, C[k], 4h+RO[k], 4w+CO[k]], k = 4*i+j.
// Packed per-class offset delta = (C<<20) | (RO<<10) | CO, added to
// base = (b*12)<<20 | (4h)<<10 | 4w.  (k=15 duplicates k=3.)
__constant__ int kDelta[16] = {
    (0<<20)|(0<<10)|0,  (3<<20)|(0<<10)|1,  (1<<20)|(0<<10)|2,  (4<<20)|(0<<10)|3,
    (6<<20)|(1<<10)|0,  (9<<20)|(1<<10)|1,  (7<<20)|(1<<10)|2, (10<<20)|(1<<10)|3,
    (1<<20)|(2<<10)|0,  (4<<20)|(2<<10)|1,  (8<<20)|(3<<10)|0, (10<<20)|(3<<10)|1,
    (2<<20)|(2<<10)|2,  (5<<20)|(2<<10)|3,  (9<<20)|(3<<10)|2,  (4<<20)|(0<<10)|3
};

#define NITEMS  8192          // 8 b * 256 h-tiles * 4 col-chunks
#define NBLK    1184          // 148 SMs * 8 resident blocks: exactly one wave
#define N_TOTAL 8388608.0f

__device__ float        g_partials[NITEMS];
__device__ unsigned int g_ticket = 0;
__device__ unsigned int g_done   = 0;

__global__ void __launch_bounds__(256, 8)
loss_fused(const float* __restrict__ x, const float* __restrict__ y,
           float* __restrict__ out)
{
    const int tid  = threadIdx.x;
    const int lane = tid & 31;
    const int warp = tid >> 5;

    __shared__ float        sm[8];
    __shared__ unsigned int s_it;
    __shared__ bool         s_last;

    for (;;) {
        if (tid == 0) s_it = atomicAdd(&g_ticket, 1u);
        __syncthreads();
        const unsigned int it = s_it;
        if (it >= NITEMS) break;

        // item -> (b, h, col-chunk); consecutive items are adjacent addresses
        const int chunk = it & 3;
        const int h     = (it >> 2) & 255;
        const int b     = it >> 10;

        // thread -> (row phase i, quad column wq); i uniform per warp
        const int i  = tid >> 6;
        const int wq = (chunk << 6) + (tid & 63);

        // x: fully coalesced float4 (read-once -> streaming hint)
        const float4 xv = __ldcs(reinterpret_cast<const float4*>(
            x + ((((size_t)(b << 10)) + (h << 2) + i) << 10) + (wq << 2)));

        const size_t ybase = (((size_t)(b * 12)) << 20)
                           + ((size_t)(h << 2) << 10) + (wq << 2);
        const int kb = i << 2;
        const float y0 = __ldcs(y + ybase + kDelta[kb + 0]);
        const float y1 = __ldcs(y + ybase + kDelta[kb + 1]);
        const float y2 = __ldcs(y + ybase + kDelta[kb + 2]);
        const float y3 = __ldcs(y + ybase + kDelta[kb + 3]);

        float s = fabsf(y0 - xv.x) + fabsf(y1 - xv.y)
                + fabsf(y2 - xv.z) + fabsf(y3 - xv.w);

        // deterministic block reduction for this item
        #pragma unroll
        for (int m = 16; m > 0; m >>= 1)
            s += __shfl_xor_sync(0xFFFFFFFFu, s, m);
        if (lane == 0) sm[warp] = s;
        __syncthreads();
        if (tid == 0) {
            float v = 0.0f;
            #pragma unroll
            for (int w = 0; w < 8; w++) v += sm[w];
            g_partials[it] = v;   // keyed by item id -> bitwise deterministic
        }
        // next iteration's ticket-__syncthreads orders sm reuse; no extra sync
    }

    // block done: last of NBLK blocks performs the fixed-order final sum
    __threadfence();
    if (tid == 0) {
        unsigned int prev = atomicAdd(&g_done, 1u);
        s_last = (prev == NBLK - 1);
    }
    __syncthreads();

    if (s_last) {
        float t = 0.0f;
        #pragma unroll 8
        for (int idx = tid; idx < NITEMS; idx += 256)
            t += g_partials[idx];
        #pragma unroll
        for (int m = 16; m > 0; m >>= 1)
            t += __shfl_xor_sync(0xFFFFFFFFu, t, m);
        if (lane == 0) sm[warp] = t;
        __syncthreads();
        if (tid == 0) {
            float v = 0.0f;
            #pragma unroll
            for (int w = 0; w < 8; w++) v += sm[w];
            out[0] = v * (1.0f / N_TOTAL);
            g_ticket = 0;   // reset device state for next graph replay
            g_done   = 0;
        }
    }
}

extern "C" void kernel_launch(void* const* d_in, const int* in_sizes, int n_in,
                              void* d_out, int out_size) {
    const float* x;
    const float* y;
    if (in_sizes[0] == 8 * 1024 * 1024) {
        x = (const float*)d_in[0];
        y = (const float*)d_in[1];
    } else {
        x = (const float*)d_in[1];
        y = (const float*)d_in[0];
    }
    loss_fused<<<NBLK, 256>>>(x, y, (float*)d_out);
}